// round 11
// baseline (speedup 1.0000x reference)
#include <cuda_runtime.h>

#define NMAX 100000
#define EMAXN 1600000

// ---- scratch (device globals). 16B-aligned for float4/RED.128 ----
__device__ __align__(16) float g_xw[NMAX * 64];     // [N][64]: 0..31 x@W_rel1, 32..63 x@W_root1
__device__ __align__(16) float g_sum1[NMAX * 32];
__device__ __align__(16) float g_cnt[NMAX];
__device__ __align__(16) float g_hr[NMAX * 8];      // h@W_rel2 (pad 8)
__device__ __align__(16) float g_hroot[NMAX * 8];   // h@W_root2 (pad 8)
__device__ __align__(16) float g_sum2[NMAX * 8];
__device__ __align__(16) int2  g_sd[EMAXN];         // packed (src, dst)
__device__ int g_is64;

// ---- helpers ----
__device__ __forceinline__ void ffma2(unsigned long long& d, unsigned long long a, unsigned long long b) {
    asm("fma.rn.f32x2 %0, %1, %2, %0;" : "+l"(d) : "l"(a), "l"(b));
}
__device__ __forceinline__ unsigned long long dup2(float a) {
    unsigned long long r;
    asm("mov.b64 %0, {%1, %1};" : "=l"(r) : "f"(a));
    return r;
}
__device__ __forceinline__ float2 u2f2(unsigned long long u) {
    float2 f;
    asm("mov.b64 {%0, %1}, %2;" : "=f"(f.x), "=f"(f.y) : "l"(u));
    return f;
}
__device__ __forceinline__ void red_add4(float* p, float4 v) {
    asm volatile("red.global.add.v4.f32 [%0], {%1,%2,%3,%4};"
                 :: "l"(p), "f"(v.x), "f"(v.y), "f"(v.z), "f"(v.w) : "memory");
}

// ---- K0: zero accumulators; block 0 also sniffs int64 vs int32 layout ----
__global__ void k_zero(const int* __restrict__ ei, int N) {
    if (blockIdx.x == 0 && threadIdx.x == 0) {
        int nz = 0;
        #pragma unroll 4
        for (int i = 1; i < 256; i += 2) nz |= ei[i];
        g_is64 = (nz == 0);
    }
    int i = blockIdx.x * blockDim.x + threadIdx.x;
    int stride = gridDim.x * blockDim.x;
    float4 z = make_float4(0.f, 0.f, 0.f, 0.f);
    for (int j = i; j < N * 8; j += stride) ((float4*)g_sum1)[j] = z;   // 32 floats/node
    for (int j = i; j < N * 2; j += stride) ((float4*)g_sum2)[j] = z;   // 8 floats/node
    for (int j = i; j < N;     j += stride) g_cnt[j] = 0.f;
}

// ---- unpack indices (packed int2) + degree count ----
__global__ void __launch_bounds__(256) k_unpack(const int* __restrict__ ei, int E, int N) {
    int e = blockIdx.x * 256 + threadIdx.x;
    if (e >= E) return;
    int s, d;
    if (g_is64) { s = ei[2 * e];  d = ei[2 * E + 2 * e]; }
    else        { s = ei[e];      d = ei[E + e]; }
    if (s < 0 || s >= N) s = 0;
    if (d < 0 || d >= N) d = 0;
    g_sd[e] = make_int2(s, d);
    atomicAdd(&g_cnt[d], 1.0f);
}

// ---- K1: fused projection  g_xw = x @ [W_rel1 | W_root1]  (128 -> 64), f32x2 ----
// 128 threads, 128-node x 64-col tile, thread = 8 nodes x 8 cols, kk unrolled x2.
// (exact R9 body — measured 59.3us)
#define XPITCH 72
__global__ void __launch_bounds__(128, 4) k_gemm1(
    const float* __restrict__ x,
    const float* __restrict__ Wrel,
    const float* __restrict__ Wroot,
    int N)
{
    extern __shared__ float sm[];
    float* Ws = sm;              // [64 k][64 c]      (4096 floats)
    float* Xs = sm + 4096;       // [128 node][72]    (9216 floats)

    const int t  = threadIdx.x;
    const int tx = t & 7;        // col group: cols tx*8 .. +7
    const int ty = t >> 3;       // node group: nodes ty*8 .. +7
    const int n0 = blockIdx.x * 128;

    unsigned long long acc[8][4];
    #pragma unroll
    for (int i = 0; i < 8; i++)
        #pragma unroll
        for (int j = 0; j < 4; j++) acc[i][j] = 0ull;

    for (int kc = 0; kc < 128; kc += 64) {
        #pragma unroll
        for (int i = t; i < 4096; i += 128) {
            int kk = i >> 6, col = i & 63;
            Ws[i] = (col < 32) ? Wrel[(kc + kk) * 32 + col]
                               : Wroot[(kc + kk) * 32 + (col - 32)];
        }
        #pragma unroll
        for (int j = 0; j < 16; j++) {
            int idx  = t + 128 * j;          // 0..2047 float4 slots
            int kq   = idx & 15;
            int node = idx >> 4;
            int gn   = n0 + node;
            float4 v = (gn < N) ? *(const float4*)&x[gn * 128 + kc + kq * 4]
                                : make_float4(0.f, 0.f, 0.f, 0.f);
            float* dst = &Xs[node * XPITCH + kq * 4];
            dst[0] = v.x; dst[1] = v.y; dst[2] = v.z; dst[3] = v.w;
        }
        __syncthreads();

        const float* xrow = &Xs[(ty * 8) * XPITCH];
        #pragma unroll 2
        for (int kk = 0; kk < 64; kk += 2) {
            ulonglong2 a01 = *(const ulonglong2*)&Ws[kk * 64 + tx * 8];
            ulonglong2 a23 = *(const ulonglong2*)&Ws[kk * 64 + tx * 8 + 4];
            ulonglong2 b01 = *(const ulonglong2*)&Ws[(kk + 1) * 64 + tx * 8];
            ulonglong2 b23 = *(const ulonglong2*)&Ws[(kk + 1) * 64 + tx * 8 + 4];
            #pragma unroll
            for (int i = 0; i < 8; i++) {
                float2 xp = *(const float2*)&xrow[i * XPITCH + kk];
                unsigned long long ax = dup2(xp.x);
                unsigned long long ay = dup2(xp.y);
                ffma2(acc[i][0], ax, a01.x);
                ffma2(acc[i][1], ax, a01.y);
                ffma2(acc[i][2], ax, a23.x);
                ffma2(acc[i][3], ax, a23.y);
                ffma2(acc[i][0], ay, b01.x);
                ffma2(acc[i][1], ay, b01.y);
                ffma2(acc[i][2], ay, b23.x);
                ffma2(acc[i][3], ay, b23.y);
            }
        }
        __syncthreads();
    }

    #pragma unroll
    for (int i = 0; i < 8; i++) {
        int node = n0 + ty * 8 + i;
        if (node < N) {
            float2 p0 = u2f2(acc[i][0]), p1 = u2f2(acc[i][1]);
            float2 p2 = u2f2(acc[i][2]), p3 = u2f2(acc[i][3]);
            *(float4*)&g_xw[node * 64 + tx * 8]     = make_float4(p0.x, p0.y, p1.x, p1.y);
            *(float4*)&g_xw[node * 64 + tx * 8 + 4] = make_float4(p2.x, p2.y, p3.x, p3.y);
        }
    }
}

// ---- edge pass 1 (weighted): 4 threads/edge, direct loads, 2x(LDG.128+RED.128) ----
__global__ void __launch_bounds__(256) k_edge1(const float* __restrict__ ew, int E) {
    int t = blockIdx.x * 256 + threadIdx.x;
    int e = t >> 2, p = t & 3;
    if (e >= E) return;
    int2 sd = g_sd[e];
    float w = ew[e];
    const float* srow = &g_xw[sd.x * 64 + p * 8];
    float4 v0 = *(const float4*)(srow);
    float4 v1 = *(const float4*)(srow + 4);
    v0.x *= w; v0.y *= w; v0.z *= w; v0.w *= w;
    v1.x *= w; v1.y *= w; v1.z *= w; v1.w *= w;
    float* dp = &g_sum1[sd.y * 32 + p * 8];
    red_add4(dp,     v0);
    red_add4(dp + 4, v1);
}

// ---- combine layer 1 + project layer 2 ----
__global__ void __launch_bounds__(256) k_comb1(
    const float* __restrict__ b1,
    const float* __restrict__ Wrel2,    // [32][5]
    const float* __restrict__ Wroot2,   // [32][5]
    int N)
{
    __shared__ float sW[352];
    int t = threadIdx.x;
    for (int i = t; i < 352; i += 256) {
        sW[i] = (i < 160) ? Wrel2[i]
              : (i < 320) ? Wroot2[i - 160]
                          : b1[i - 320];
    }
    __syncthreads();

    int node = blockIdx.x * 256 + t;
    if (node >= N) return;

    float inv = 1.0f / fmaxf(g_cnt[node], 1.0f);
    const float4* sp = (const float4*)&g_sum1[node * 32];
    const float4* rp = (const float4*)&g_xw[node * 64 + 32];

    float h[32];
    #pragma unroll
    for (int q = 0; q < 8; q++) {
        float4 s4 = sp[q];
        float4 r4 = rp[q];
        h[4 * q + 0] = fmaxf(s4.x * inv + r4.x + sW[320 + 4 * q + 0], 0.f);
        h[4 * q + 1] = fmaxf(s4.y * inv + r4.y + sW[320 + 4 * q + 1], 0.f);
        h[4 * q + 2] = fmaxf(s4.z * inv + r4.z + sW[320 + 4 * q + 2], 0.f);
        h[4 * q + 3] = fmaxf(s4.w * inv + r4.w + sW[320 + 4 * q + 3], 0.f);
    }

    float hr[5] = {0.f, 0.f, 0.f, 0.f, 0.f};
    float ho[5] = {0.f, 0.f, 0.f, 0.f, 0.f};
    #pragma unroll
    for (int j = 0; j < 32; j++) {
        float hv = h[j];
        #pragma unroll
        for (int c = 0; c < 5; c++) {
            hr[c] += hv * sW[j * 5 + c];
            ho[c] += hv * sW[160 + j * 5 + c];
        }
    }
    *(float4*)&g_hr[node * 8 + 0]    = make_float4(hr[0], hr[1], hr[2], hr[3]);
    *(float4*)&g_hr[node * 8 + 4]    = make_float4(hr[4], 0.f, 0.f, 0.f);
    *(float4*)&g_hroot[node * 8 + 0] = make_float4(ho[0], ho[1], ho[2], ho[3]);
    *(float4*)&g_hroot[node * 8 + 4] = make_float4(ho[4], 0.f, 0.f, 0.f);
}

// ---- edge pass 2: 2 threads/edge, packed int2 index, LDG.128 + RED.128 ----
__global__ void __launch_bounds__(256) k_edge2(int E) {
    int t = blockIdx.x * 256 + threadIdx.x;
    int e = t >> 1, p = t & 1;
    if (e >= E) return;
    int2 sd = g_sd[e];
    float4 v = *(const float4*)&g_hr[sd.x * 8 + p * 4];
    red_add4(&g_sum2[sd.y * 8 + p * 4], v);
}

// ---- combine layer 2 + log_softmax ----
__global__ void __launch_bounds__(256) k_final(
    const float* __restrict__ b2,
    float* __restrict__ out,
    int N)
{
    int node = blockIdx.x * 256 + threadIdx.x;
    if (node >= N) return;
    float inv = 1.0f / fmaxf(g_cnt[node], 1.0f);
    float v[5];
    #pragma unroll
    for (int c = 0; c < 5; c++)
        v[c] = g_sum2[node * 8 + c] * inv + g_hroot[node * 8 + c] + b2[c];

    float m = v[0];
    #pragma unroll
    for (int c = 1; c < 5; c++) m = fmaxf(m, v[c]);
    float sum = 0.f;
    #pragma unroll
    for (int c = 0; c < 5; c++) sum += expf(v[c] - m);
    float lse = m + logf(sum);
    #pragma unroll
    for (int c = 0; c < 5; c++) out[node * 5 + c] = v[c] - lse;
}

extern "C" void kernel_launch(void* const* d_in, const int* in_sizes, int n_in,
                              void* d_out, int out_size)
{
    const float* x      = (const float*)d_in[0];
    const int*   ei     = (const int*)d_in[1];
    const float* ew     = (const float*)d_in[2];
    const float* Wrel1  = (const float*)d_in[3];
    const float* Wroot1 = (const float*)d_in[4];
    const float* b1     = (const float*)d_in[5];
    const float* Wrel2  = (const float*)d_in[6];
    const float* Wroot2 = (const float*)d_in[7];
    const float* b2     = (const float*)d_in[8];
    float*       out    = (float*)d_out;

    int N = out_size / 5;          // output [N,5]
    int E = in_sizes[1] / 2;       // edge_index [2,E]

    const int GEMM_SMEM = (4096 + 128 * XPITCH) * 4;   // 53248 B
    cudaFuncSetAttribute(k_gemm1, cudaFuncAttributeMaxDynamicSharedMemorySize, GEMM_SMEM);

    k_zero  <<<1024, 256>>>(ei, N);
    k_unpack<<<(E + 255) / 256, 256>>>(ei, E, N);
    k_gemm1 <<<(N + 127) / 128, 128, GEMM_SMEM>>>(x, Wrel1, Wroot1, N);
    k_edge1 <<<(E * 4 + 255) / 256, 256>>>(ew, E);
    k_comb1 <<<(N + 255) / 256, 256>>>(b1, Wrel2, Wroot2, N);
    k_edge2 <<<(E * 2 + 255) / 256, 256>>>(E);
    k_final <<<(N + 255) / 256, 256>>>(b2, out, N);
}

// round 12
// speedup vs baseline: 1.1472x; 1.1472x over previous
#include <cuda_runtime.h>

#define NMAX 100000
#define EMAXN 1600000

// ---- scratch (device globals). 16B-aligned for float4/RED.128 ----
__device__ __align__(16) float g_xw[NMAX * 64];     // [N][64]: 0..31 x@W_rel1, 32..63 x@W_root1
__device__ __align__(16) float g_sum1[NMAX * 32];
__device__ __align__(16) float g_cnt[NMAX];
__device__ __align__(16) float g_hr[NMAX * 8];      // h@W_rel2 (pad 8)
__device__ __align__(16) float g_hroot[NMAX * 8];   // h@W_root2 (pad 8)
__device__ __align__(16) float g_sum2[NMAX * 8];
__device__ __align__(16) int2  g_sd[EMAXN];         // packed (src, dst)
__device__ int g_is64;

// ---- helpers ----
__device__ __forceinline__ void ffma2(unsigned long long& d, unsigned long long a, unsigned long long b) {
    asm("fma.rn.f32x2 %0, %1, %2, %0;" : "+l"(d) : "l"(a), "l"(b));
}
__device__ __forceinline__ unsigned long long dup2(float a) {
    unsigned long long r;
    asm("mov.b64 %0, {%1, %1};" : "=l"(r) : "f"(a));
    return r;
}
__device__ __forceinline__ float2 u2f2(unsigned long long u) {
    float2 f;
    asm("mov.b64 {%0, %1}, %2;" : "=f"(f.x), "=f"(f.y) : "l"(u));
    return f;
}
__device__ __forceinline__ void red_add4(float* p, float4 v) {
    asm volatile("red.global.add.v4.f32 [%0], {%1,%2,%3,%4};"
                 :: "l"(p), "f"(v.x), "f"(v.y), "f"(v.z), "f"(v.w) : "memory");
}

// ---- K0: zero g_cnt (tiny) + sniff int64 vs int32 layout ----
__global__ void k_zc(const int* __restrict__ ei, int N) {
    if (blockIdx.x == 0 && threadIdx.x == 0) {
        int nz = 0;
        #pragma unroll 4
        for (int i = 1; i < 256; i += 2) nz |= ei[i];
        g_is64 = (nz == 0);
    }
    int i = blockIdx.x * blockDim.x + threadIdx.x;
    if (i < N) g_cnt[i] = 0.f;
}

// ---- unpack indices (packed int2) + degree count ----
__global__ void __launch_bounds__(256) k_unpack(const int* __restrict__ ei, int E, int N) {
    int e = blockIdx.x * 256 + threadIdx.x;
    if (e >= E) return;
    int s, d;
    if (g_is64) { s = ei[2 * e];  d = ei[2 * E + 2 * e]; }
    else        { s = ei[e];      d = ei[E + e]; }
    if (s < 0 || s >= N) s = 0;
    if (d < 0 || d >= N) d = 0;
    g_sd[e] = make_int2(s, d);
    atomicAdd(&g_cnt[d], 1.0f);
}

// ---- K1: fused projection  g_xw = x @ [W_rel1 | W_root1], bank-conflict-free ----
// 128 threads, 128-node x 64-col tile. Thread = nodes {ty+16i} x cols {tx*4..+3, 32+tx*4..+3}.
// Epilogue also zeros g_sum1/g_sum2 for this block's nodes.
#define XPITCH 68
__global__ void __launch_bounds__(128, 4) k_gemm1(
    const float* __restrict__ x,
    const float* __restrict__ Wrel,
    const float* __restrict__ Wroot,
    int N)
{
    extern __shared__ float sm[];
    float* Ws = sm;              // [64 k][64 c]      (4096 floats)
    float* Xs = sm + 4096;       // [128 node][68]    (8704 floats)

    const int t  = threadIdx.x;
    const int tx = t & 7;        // col groups: tx*4..+3 and 32+tx*4..+3
    const int ty = t >> 3;       // node base: nodes ty, ty+16, ..., ty+112
    const int n0 = blockIdx.x * 128;

    unsigned long long acc[8][4];
    #pragma unroll
    for (int i = 0; i < 8; i++)
        #pragma unroll
        for (int j = 0; j < 4; j++) acc[i][j] = 0ull;

    for (int kc = 0; kc < 128; kc += 64) {
        // stage W chunk [64 k][64 c]
        #pragma unroll
        for (int i = t; i < 4096; i += 128) {
            int kk = i >> 6, col = i & 63;
            Ws[i] = (col < 32) ? Wrel[(kc + kk) * 32 + col]
                               : Wroot[(kc + kk) * 32 + (col - 32)];
        }
        // stage X chunk [128 node][64 k], coalesced float4 gmem reads
        #pragma unroll
        for (int j = 0; j < 16; j++) {
            int idx  = t + 128 * j;          // 0..2047 float4 slots
            int kq   = idx & 15;
            int node = idx >> 4;
            int gn   = n0 + node;
            float4 v = (gn < N) ? *(const float4*)&x[gn * 128 + kc + kq * 4]
                                : make_float4(0.f, 0.f, 0.f, 0.f);
            *(float4*)&Xs[node * XPITCH + kq * 4] = v;
        }
        __syncthreads();

        #pragma unroll 2
        for (int kk = 0; kk < 64; kk += 2) {
            // W: 8 distinct 16B superbanks per load -> conflict-free
            ulonglong2 a0 = *(const ulonglong2*)&Ws[kk * 64 + tx * 4];
            ulonglong2 a1 = *(const ulonglong2*)&Ws[kk * 64 + 32 + tx * 4];
            ulonglong2 b0 = *(const ulonglong2*)&Ws[(kk + 1) * 64 + tx * 4];
            ulonglong2 b1 = *(const ulonglong2*)&Ws[(kk + 1) * 64 + 32 + tx * 4];
            #pragma unroll
            for (int i = 0; i < 8; i++) {
                // X: ty-lanes spread over distinct banks (stride 16*68 === 0, ty*68 spreads)
                float2 xp = *(const float2*)&Xs[(ty + 16 * i) * XPITCH + kk];
                unsigned long long ax = dup2(xp.x);
                unsigned long long ay = dup2(xp.y);
                ffma2(acc[i][0], ax, a0.x);
                ffma2(acc[i][1], ax, a0.y);
                ffma2(acc[i][2], ax, a1.x);
                ffma2(acc[i][3], ax, a1.y);
                ffma2(acc[i][0], ay, b0.x);
                ffma2(acc[i][1], ay, b0.y);
                ffma2(acc[i][2], ay, b1.x);
                ffma2(acc[i][3], ay, b1.y);
            }
        }
        __syncthreads();
    }

    #pragma unroll
    for (int i = 0; i < 8; i++) {
        int node = n0 + ty + 16 * i;
        if (node < N) {
            float2 p0 = u2f2(acc[i][0]), p1 = u2f2(acc[i][1]);
            float2 p2 = u2f2(acc[i][2]), p3 = u2f2(acc[i][3]);
            *(float4*)&g_xw[node * 64 + tx * 4]      = make_float4(p0.x, p0.y, p1.x, p1.y);
            *(float4*)&g_xw[node * 64 + 32 + tx * 4] = make_float4(p2.x, p2.y, p3.x, p3.y);
        }
    }

    // epilogue: zero this block's slices of g_sum1 / g_sum2 (one node per thread)
    {
        int node = n0 + t;
        if (node < N) {
            float4 z = make_float4(0.f, 0.f, 0.f, 0.f);
            float4* s1 = (float4*)&g_sum1[node * 32];
            #pragma unroll
            for (int q = 0; q < 8; q++) s1[q] = z;
            float4* s2 = (float4*)&g_sum2[node * 8];
            s2[0] = z; s2[1] = z;
        }
    }
}

// ---- edge pass 1 (weighted): 8 threads/edge, direct loads, LDG.128 + RED.128 ----
__global__ void __launch_bounds__(256) k_edge1(const float* __restrict__ ew, int E) {
    int t = blockIdx.x * 256 + threadIdx.x;
    int e = t >> 3, p = t & 7;
    if (e >= E) return;
    int2 sd = g_sd[e];
    float w = ew[e];
    float4 v = *(const float4*)&g_xw[sd.x * 64 + p * 4];   // rel-projected cols 0..31
    v.x *= w; v.y *= w; v.z *= w; v.w *= w;
    red_add4(&g_sum1[sd.y * 32 + p * 4], v);
}

// ---- combine layer 1 + project layer 2 ----
__global__ void __launch_bounds__(256) k_comb1(
    const float* __restrict__ b1,
    const float* __restrict__ Wrel2,    // [32][5]
    const float* __restrict__ Wroot2,   // [32][5]
    int N)
{
    __shared__ float sW[352];
    int t = threadIdx.x;
    for (int i = t; i < 352; i += 256) {
        sW[i] = (i < 160) ? Wrel2[i]
              : (i < 320) ? Wroot2[i - 160]
                          : b1[i - 320];
    }
    __syncthreads();

    int node = blockIdx.x * 256 + t;
    if (node >= N) return;

    float inv = 1.0f / fmaxf(g_cnt[node], 1.0f);
    const float4* sp = (const float4*)&g_sum1[node * 32];
    const float4* rp = (const float4*)&g_xw[node * 64 + 32];

    float h[32];
    #pragma unroll
    for (int q = 0; q < 8; q++) {
        float4 s4 = sp[q];
        float4 r4 = rp[q];
        h[4 * q + 0] = fmaxf(s4.x * inv + r4.x + sW[320 + 4 * q + 0], 0.f);
        h[4 * q + 1] = fmaxf(s4.y * inv + r4.y + sW[320 + 4 * q + 1], 0.f);
        h[4 * q + 2] = fmaxf(s4.z * inv + r4.z + sW[320 + 4 * q + 2], 0.f);
        h[4 * q + 3] = fmaxf(s4.w * inv + r4.w + sW[320 + 4 * q + 3], 0.f);
    }

    float hr[5] = {0.f, 0.f, 0.f, 0.f, 0.f};
    float ho[5] = {0.f, 0.f, 0.f, 0.f, 0.f};
    #pragma unroll
    for (int j = 0; j < 32; j++) {
        float hv = h[j];
        #pragma unroll
        for (int c = 0; c < 5; c++) {
            hr[c] += hv * sW[j * 5 + c];
            ho[c] += hv * sW[160 + j * 5 + c];
        }
    }
    *(float4*)&g_hr[node * 8 + 0]    = make_float4(hr[0], hr[1], hr[2], hr[3]);
    *(float4*)&g_hr[node * 8 + 4]    = make_float4(hr[4], 0.f, 0.f, 0.f);
    *(float4*)&g_hroot[node * 8 + 0] = make_float4(ho[0], ho[1], ho[2], ho[3]);
    *(float4*)&g_hroot[node * 8 + 4] = make_float4(ho[4], 0.f, 0.f, 0.f);
}

// ---- edge pass 2: 2 threads/edge, packed int2 index, LDG.128 + RED.128 ----
__global__ void __launch_bounds__(256) k_edge2(int E) {
    int t = blockIdx.x * 256 + threadIdx.x;
    int e = t >> 1, p = t & 1;
    if (e >= E) return;
    int2 sd = g_sd[e];
    float4 v = *(const float4*)&g_hr[sd.x * 8 + p * 4];
    red_add4(&g_sum2[sd.y * 8 + p * 4], v);
}

// ---- combine layer 2 + log_softmax ----
__global__ void __launch_bounds__(256) k_final(
    const float* __restrict__ b2,
    float* __restrict__ out,
    int N)
{
    int node = blockIdx.x * 256 + threadIdx.x;
    if (node >= N) return;
    float inv = 1.0f / fmaxf(g_cnt[node], 1.0f);
    float v[5];
    #pragma unroll
    for (int c = 0; c < 5; c++)
        v[c] = g_sum2[node * 8 + c] * inv + g_hroot[node * 8 + c] + b2[c];

    float m = v[0];
    #pragma unroll
    for (int c = 1; c < 5; c++) m = fmaxf(m, v[c]);
    float sum = 0.f;
    #pragma unroll
    for (int c = 0; c < 5; c++) sum += expf(v[c] - m);
    float lse = m + logf(sum);
    #pragma unroll
    for (int c = 0; c < 5; c++) out[node * 5 + c] = v[c] - lse;
}

extern "C" void kernel_launch(void* const* d_in, const int* in_sizes, int n_in,
                              void* d_out, int out_size)
{
    const float* x      = (const float*)d_in[0];
    const int*   ei     = (const int*)d_in[1];
    const float* ew     = (const float*)d_in[2];
    const float* Wrel1  = (const float*)d_in[3];
    const float* Wroot1 = (const float*)d_in[4];
    const float* b1     = (const float*)d_in[5];
    const float* Wrel2  = (const float*)d_in[6];
    const float* Wroot2 = (const float*)d_in[7];
    const float* b2     = (const float*)d_in[8];
    float*       out    = (float*)d_out;

    int N = out_size / 5;          // output [N,5]
    int E = in_sizes[1] / 2;       // edge_index [2,E]

    const int GEMM_SMEM = (4096 + 128 * XPITCH) * 4;   // 51200 B
    cudaFuncSetAttribute(k_gemm1, cudaFuncAttributeMaxDynamicSharedMemorySize, GEMM_SMEM);

    k_zc    <<<(N + 255) / 256, 256>>>(ei, N);
    k_unpack<<<(E + 255) / 256, 256>>>(ei, E, N);
    k_gemm1 <<<(N + 127) / 128, 128, GEMM_SMEM>>>(x, Wrel1, Wroot1, N);
    k_edge1 <<<(E * 8 + 255) / 256, 256>>>(ew, E);
    k_comb1 <<<(N + 255) / 256, 256>>>(b1, Wrel2, Wroot2, N);
    k_edge2 <<<(E * 2 + 255) / 256, 256>>>(E);
    k_final <<<(N + 255) / 256, 256>>>(b2, out, N);
}

// round 13
// speedup vs baseline: 1.2747x; 1.1111x over previous
#include <cuda_runtime.h>

#define NMAX 100000
#define EMAXN 1600000

// ---- scratch (device globals). 16B-aligned for float4/RED.128 ----
__device__ __align__(16) float g_xw[NMAX * 64];     // [N][64]: 0..31 x@W_rel1, 32..63 x@W_root1
__device__ __align__(16) float g_sum1[NMAX * 32];
__device__ __align__(16) float g_cnt[NMAX];
__device__ __align__(16) float g_hr[NMAX * 8];      // h@W_rel2 (pad 8)
__device__ __align__(16) float g_hroot[NMAX * 8];   // h@W_root2 (pad 8)
__device__ __align__(16) float g_sum2[NMAX * 8];
__device__ __align__(16) int4  g_sdw[EMAXN];        // packed (src, dst, weight-bits, 0)
__device__ int g_is64;

// ---- helpers ----
__device__ __forceinline__ void ffma2(unsigned long long& d, unsigned long long a, unsigned long long b) {
    asm("fma.rn.f32x2 %0, %1, %2, %0;" : "+l"(d) : "l"(a), "l"(b));
}
__device__ __forceinline__ unsigned long long dup2(float a) {
    unsigned long long r;
    asm("mov.b64 %0, {%1, %1};" : "=l"(r) : "f"(a));
    return r;
}
__device__ __forceinline__ float2 u2f2(unsigned long long u) {
    float2 f;
    asm("mov.b64 {%0, %1}, %2;" : "=f"(f.x), "=f"(f.y) : "l"(u));
    return f;
}
__device__ __forceinline__ void red_add4(float* p, float4 v) {
    asm volatile("red.global.add.v4.f32 [%0], {%1,%2,%3,%4};"
                 :: "l"(p), "f"(v.x), "f"(v.y), "f"(v.z), "f"(v.w) : "memory");
}

// ---- K0: zero g_cnt (tiny) + sniff int64 vs int32 layout ----
__global__ void k_zc(const int* __restrict__ ei, int N) {
    if (blockIdx.x == 0 && threadIdx.x == 0) {
        int nz = 0;
        #pragma unroll 4
        for (int i = 1; i < 256; i += 2) nz |= ei[i];
        g_is64 = (nz == 0);
    }
    int i = blockIdx.x * blockDim.x + threadIdx.x;
    if (i < N) g_cnt[i] = 0.f;
}

// ---- unpack indices (packed int4 with weight) + degree count ----
__global__ void __launch_bounds__(256) k_unpack(const int* __restrict__ ei,
                                                const float* __restrict__ ew,
                                                int E, int N) {
    int e = blockIdx.x * 256 + threadIdx.x;
    if (e >= E) return;
    int s, d;
    if (g_is64) { s = ei[2 * e];  d = ei[2 * E + 2 * e]; }
    else        { s = ei[e];      d = ei[E + e]; }
    if (s < 0 || s >= N) s = 0;
    if (d < 0 || d >= N) d = 0;
    g_sdw[e] = make_int4(s, d, __float_as_int(ew[e]), 0);
    atomicAdd(&g_cnt[d], 1.0f);
}

// ---- K1: fused projection  g_xw = x @ [W_rel1 | W_root1], bank-conflict-free ----
// 128 threads, 128-node x 64-col tile. Thread = nodes {ty+16i} x cols {tx*4..+3, 32+tx*4..+3}.
// Epilogue also zeros g_sum1/g_sum2 for this block's nodes. (measured-best R12 body)
#define XPITCH 68
__global__ void __launch_bounds__(128, 4) k_gemm1(
    const float* __restrict__ x,
    const float* __restrict__ Wrel,
    const float* __restrict__ Wroot,
    int N)
{
    extern __shared__ float sm[];
    float* Ws = sm;              // [64 k][64 c]      (4096 floats)
    float* Xs = sm + 4096;       // [128 node][68]    (8704 floats)

    const int t  = threadIdx.x;
    const int tx = t & 7;
    const int ty = t >> 3;
    const int n0 = blockIdx.x * 128;

    unsigned long long acc[8][4];
    #pragma unroll
    for (int i = 0; i < 8; i++)
        #pragma unroll
        for (int j = 0; j < 4; j++) acc[i][j] = 0ull;

    for (int kc = 0; kc < 128; kc += 64) {
        #pragma unroll
        for (int i = t; i < 4096; i += 128) {
            int kk = i >> 6, col = i & 63;
            Ws[i] = (col < 32) ? Wrel[(kc + kk) * 32 + col]
                               : Wroot[(kc + kk) * 32 + (col - 32)];
        }
        #pragma unroll
        for (int j = 0; j < 16; j++) {
            int idx  = t + 128 * j;
            int kq   = idx & 15;
            int node = idx >> 4;
            int gn   = n0 + node;
            float4 v = (gn < N) ? *(const float4*)&x[gn * 128 + kc + kq * 4]
                                : make_float4(0.f, 0.f, 0.f, 0.f);
            *(float4*)&Xs[node * XPITCH + kq * 4] = v;
        }
        __syncthreads();

        #pragma unroll 2
        for (int kk = 0; kk < 64; kk += 2) {
            ulonglong2 a0 = *(const ulonglong2*)&Ws[kk * 64 + tx * 4];
            ulonglong2 a1 = *(const ulonglong2*)&Ws[kk * 64 + 32 + tx * 4];
            ulonglong2 b0 = *(const ulonglong2*)&Ws[(kk + 1) * 64 + tx * 4];
            ulonglong2 b1 = *(const ulonglong2*)&Ws[(kk + 1) * 64 + 32 + tx * 4];
            #pragma unroll
            for (int i = 0; i < 8; i++) {
                float2 xp = *(const float2*)&Xs[(ty + 16 * i) * XPITCH + kk];
                unsigned long long ax = dup2(xp.x);
                unsigned long long ay = dup2(xp.y);
                ffma2(acc[i][0], ax, a0.x);
                ffma2(acc[i][1], ax, a0.y);
                ffma2(acc[i][2], ax, a1.x);
                ffma2(acc[i][3], ax, a1.y);
                ffma2(acc[i][0], ay, b0.x);
                ffma2(acc[i][1], ay, b0.y);
                ffma2(acc[i][2], ay, b1.x);
                ffma2(acc[i][3], ay, b1.y);
            }
        }
        __syncthreads();
    }

    #pragma unroll
    for (int i = 0; i < 8; i++) {
        int node = n0 + ty + 16 * i;
        if (node < N) {
            float2 p0 = u2f2(acc[i][0]), p1 = u2f2(acc[i][1]);
            float2 p2 = u2f2(acc[i][2]), p3 = u2f2(acc[i][3]);
            *(float4*)&g_xw[node * 64 + tx * 4]      = make_float4(p0.x, p0.y, p1.x, p1.y);
            *(float4*)&g_xw[node * 64 + 32 + tx * 4] = make_float4(p2.x, p2.y, p3.x, p3.y);
        }
    }

    // epilogue: zero this block's slices of g_sum1 / g_sum2
    {
        int node = n0 + t;
        if (node < N) {
            float4 z = make_float4(0.f, 0.f, 0.f, 0.f);
            float4* s1 = (float4*)&g_sum1[node * 32];
            #pragma unroll
            for (int q = 0; q < 8; q++) s1[q] = z;
            float4* s2 = (float4*)&g_sum2[node * 8];
            s2[0] = z; s2[1] = z;
        }
    }
}

// ---- edge pass 1 (weighted): 8 threads/edge, one LDG.128 for metadata ----
__global__ void __launch_bounds__(256) k_edge1(int E) {
    int t = blockIdx.x * 256 + threadIdx.x;
    int e = t >> 3, p = t & 7;
    if (e >= E) return;
    int4 sdw = g_sdw[e];
    float w = __int_as_float(sdw.z);
    float4 v = *(const float4*)&g_xw[sdw.x * 64 + p * 4];   // rel-projected cols 0..31
    v.x *= w; v.y *= w; v.z *= w; v.w *= w;
    red_add4(&g_sum1[sdw.y * 32 + p * 4], v);
}

// ---- combine layer 1 + project layer 2 ----
__global__ void __launch_bounds__(256) k_comb1(
    const float* __restrict__ b1,
    const float* __restrict__ Wrel2,    // [32][5]
    const float* __restrict__ Wroot2,   // [32][5]
    int N)
{
    __shared__ float sW[352];
    int t = threadIdx.x;
    for (int i = t; i < 352; i += 256) {
        sW[i] = (i < 160) ? Wrel2[i]
              : (i < 320) ? Wroot2[i - 160]
                          : b1[i - 320];
    }
    __syncthreads();

    int node = blockIdx.x * 256 + t;
    if (node >= N) return;

    float inv = 1.0f / fmaxf(g_cnt[node], 1.0f);
    const float4* sp = (const float4*)&g_sum1[node * 32];
    const float4* rp = (const float4*)&g_xw[node * 64 + 32];

    float h[32];
    #pragma unroll
    for (int q = 0; q < 8; q++) {
        float4 s4 = sp[q];
        float4 r4 = rp[q];
        h[4 * q + 0] = fmaxf(s4.x * inv + r4.x + sW[320 + 4 * q + 0], 0.f);
        h[4 * q + 1] = fmaxf(s4.y * inv + r4.y + sW[320 + 4 * q + 1], 0.f);
        h[4 * q + 2] = fmaxf(s4.z * inv + r4.z + sW[320 + 4 * q + 2], 0.f);
        h[4 * q + 3] = fmaxf(s4.w * inv + r4.w + sW[320 + 4 * q + 3], 0.f);
    }

    float hr[5] = {0.f, 0.f, 0.f, 0.f, 0.f};
    float ho[5] = {0.f, 0.f, 0.f, 0.f, 0.f};
    #pragma unroll
    for (int j = 0; j < 32; j++) {
        float hv = h[j];
        #pragma unroll
        for (int c = 0; c < 5; c++) {
            hr[c] += hv * sW[j * 5 + c];
            ho[c] += hv * sW[160 + j * 5 + c];
        }
    }
    *(float4*)&g_hr[node * 8 + 0]    = make_float4(hr[0], hr[1], hr[2], hr[3]);
    *(float4*)&g_hr[node * 8 + 4]    = make_float4(hr[4], 0.f, 0.f, 0.f);
    *(float4*)&g_hroot[node * 8 + 0] = make_float4(ho[0], ho[1], ho[2], ho[3]);
    *(float4*)&g_hroot[node * 8 + 4] = make_float4(ho[4], 0.f, 0.f, 0.f);
}

// ---- edge pass 2: 2 threads/edge, LDG.128 + RED.128 ----
__global__ void __launch_bounds__(256) k_edge2(int E) {
    int t = blockIdx.x * 256 + threadIdx.x;
    int e = t >> 1, p = t & 1;
    if (e >= E) return;
    int4 sdw = g_sdw[e];
    float4 v = *(const float4*)&g_hr[sdw.x * 8 + p * 4];
    red_add4(&g_sum2[sdw.y * 8 + p * 4], v);
}

// ---- combine layer 2 + log_softmax ----
__global__ void __launch_bounds__(256) k_final(
    const float* __restrict__ b2,
    float* __restrict__ out,
    int N)
{
    int node = blockIdx.x * 256 + threadIdx.x;
    if (node >= N) return;
    float inv = 1.0f / fmaxf(g_cnt[node], 1.0f);
    float v[5];
    #pragma unroll
    for (int c = 0; c < 5; c++)
        v[c] = g_sum2[node * 8 + c] * inv + g_hroot[node * 8 + c] + b2[c];

    float m = v[0];
    #pragma unroll
    for (int c = 1; c < 5; c++) m = fmaxf(m, v[c]);
    float sum = 0.f;
    #pragma unroll
    for (int c = 0; c < 5; c++) sum += expf(v[c] - m);
    float lse = m + logf(sum);
    #pragma unroll
    for (int c = 0; c < 5; c++) out[node * 5 + c] = v[c] - lse;
}

extern "C" void kernel_launch(void* const* d_in, const int* in_sizes, int n_in,
                              void* d_out, int out_size)
{
    const float* x      = (const float*)d_in[0];
    const int*   ei     = (const int*)d_in[1];
    const float* ew     = (const float*)d_in[2];
    const float* Wrel1  = (const float*)d_in[3];
    const float* Wroot1 = (const float*)d_in[4];
    const float* b1     = (const float*)d_in[5];
    const float* Wrel2  = (const float*)d_in[6];
    const float* Wroot2 = (const float*)d_in[7];
    const float* b2     = (const float*)d_in[8];
    float*       out    = (float*)d_out;

    int N = out_size / 5;          // output [N,5]
    int E = in_sizes[1] / 2;       // edge_index [2,E]

    const int GEMM_SMEM = (4096 + 128 * XPITCH) * 4;   // 51200 B
    cudaFuncSetAttribute(k_gemm1, cudaFuncAttributeMaxDynamicSharedMemorySize, GEMM_SMEM);

    // lazy-init side stream + events (host objects only; created on first
    // (non-capture) call, reused during graph capture)
    static cudaStream_t s2 = nullptr;
    static cudaEvent_t evFork = nullptr, evJoin = nullptr;
    if (!s2) {
        cudaStreamCreateWithFlags(&s2, cudaStreamNonBlocking);
        cudaEventCreateWithFlags(&evFork, cudaEventDisableTiming);
        cudaEventCreateWithFlags(&evJoin, cudaEventDisableTiming);
    }

    // fork: {zc -> unpack} on s2, gemm1 on main stream, join before edge1
    cudaEventRecord(evFork, 0);
    cudaStreamWaitEvent(s2, evFork, 0);
    k_zc    <<<(N + 255) / 256, 256, 0, s2>>>(ei, N);
    k_unpack<<<(E + 255) / 256, 256, 0, s2>>>(ei, ew, E, N);
    cudaEventRecord(evJoin, s2);

    k_gemm1 <<<(N + 127) / 128, 128, GEMM_SMEM>>>(x, Wrel1, Wroot1, N);
    cudaStreamWaitEvent(0, evJoin, 0);

    k_edge1 <<<(E * 8 + 255) / 256, 256>>>(E);
    k_comb1 <<<(N + 255) / 256, 256>>>(b1, Wrel2, Wroot2, N);
    k_edge2 <<<(E * 2 + 255) / 256, 256>>>(E);
    k_final <<<(N + 255) / 256, 256>>>(b2, out, N);
}

// round 14
// speedup vs baseline: 1.2989x; 1.0190x over previous
#include <cuda_runtime.h>
#include <cuda_fp16.h>

#define NMAX 100000
#define EMAXN 1600000

// ---- scratch (device globals). 16B-aligned for float4/RED.128 ----
__device__ __align__(16) __half g_xwh[NMAX * 32];   // f16 rel-projection (edge1 gather payload)
__device__ __align__(16) float g_xroot[NMAX * 32];  // fp32 root-projection (comb1)
__device__ __align__(16) float g_sum1[NMAX * 32];
__device__ __align__(16) float g_cnt[NMAX];
__device__ __align__(16) float g_hr[NMAX * 8];      // h@W_rel2 (pad 8)
__device__ __align__(16) float g_hroot[NMAX * 8];   // h@W_root2 (pad 8)
__device__ __align__(16) float g_sum2[NMAX * 8];
__device__ __align__(16) int4  g_sdw[EMAXN];        // packed (src, dst, weight-bits, 0)
__device__ int g_is64;

// ---- helpers ----
__device__ __forceinline__ void ffma2(unsigned long long& d, unsigned long long a, unsigned long long b) {
    asm("fma.rn.f32x2 %0, %1, %2, %0;" : "+l"(d) : "l"(a), "l"(b));
}
__device__ __forceinline__ unsigned long long dup2(float a) {
    unsigned long long r;
    asm("mov.b64 %0, {%1, %1};" : "=l"(r) : "f"(a));
    return r;
}
__device__ __forceinline__ float2 u2f2(unsigned long long u) {
    float2 f;
    asm("mov.b64 {%0, %1}, %2;" : "=f"(f.x), "=f"(f.y) : "l"(u));
    return f;
}
__device__ __forceinline__ void red_add4(float* p, float4 v) {
    asm volatile("red.global.add.v4.f32 [%0], {%1,%2,%3,%4};"
                 :: "l"(p), "f"(v.x), "f"(v.y), "f"(v.z), "f"(v.w) : "memory");
}

// ---- K0: zero g_cnt (tiny) + sniff int64 vs int32 layout ----
__global__ void k_zc(const int* __restrict__ ei, int N) {
    if (blockIdx.x == 0 && threadIdx.x == 0) {
        int nz = 0;
        #pragma unroll 4
        for (int i = 1; i < 256; i += 2) nz |= ei[i];
        g_is64 = (nz == 0);
    }
    int i = blockIdx.x * blockDim.x + threadIdx.x;
    if (i < N) g_cnt[i] = 0.f;
}

// ---- unpack indices (packed int4 with weight) + degree count ----
__global__ void __launch_bounds__(256) k_unpack(const int* __restrict__ ei,
                                                const float* __restrict__ ew,
                                                int E, int N) {
    int e = blockIdx.x * 256 + threadIdx.x;
    if (e >= E) return;
    int s, d;
    if (g_is64) { s = ei[2 * e];  d = ei[2 * E + 2 * e]; }
    else        { s = ei[e];      d = ei[E + e]; }
    if (s < 0 || s >= N) s = 0;
    if (d < 0 || d >= N) d = 0;
    g_sdw[e] = make_int4(s, d, __float_as_int(ew[e]), 0);
    atomicAdd(&g_cnt[d], 1.0f);
}

// ---- K1: fused projection. rel -> f16 g_xwh, root -> fp32 g_xroot ----
// 128 threads, 128-node x 64-col tile. Thread = nodes {ty+16i} x cols {tx*4..+3, 32+tx*4..+3}.
#define XPITCH 68
__global__ void __launch_bounds__(128, 4) k_gemm1(
    const float* __restrict__ x,
    const float* __restrict__ Wrel,
    const float* __restrict__ Wroot,
    int N)
{
    extern __shared__ float sm[];
    float* Ws = sm;              // [64 k][64 c]      (4096 floats)
    float* Xs = sm + 4096;       // [128 node][68]    (8704 floats)

    const int t  = threadIdx.x;
    const int tx = t & 7;
    const int ty = t >> 3;
    const int n0 = blockIdx.x * 128;

    unsigned long long acc[8][4];
    #pragma unroll
    for (int i = 0; i < 8; i++)
        #pragma unroll
        for (int j = 0; j < 4; j++) acc[i][j] = 0ull;

    for (int kc = 0; kc < 128; kc += 64) {
        #pragma unroll
        for (int i = t; i < 4096; i += 128) {
            int kk = i >> 6, col = i & 63;
            Ws[i] = (col < 32) ? Wrel[(kc + kk) * 32 + col]
                               : Wroot[(kc + kk) * 32 + (col - 32)];
        }
        #pragma unroll
        for (int j = 0; j < 16; j++) {
            int idx  = t + 128 * j;
            int kq   = idx & 15;
            int node = idx >> 4;
            int gn   = n0 + node;
            float4 v = (gn < N) ? *(const float4*)&x[gn * 128 + kc + kq * 4]
                                : make_float4(0.f, 0.f, 0.f, 0.f);
            *(float4*)&Xs[node * XPITCH + kq * 4] = v;
        }
        __syncthreads();

        #pragma unroll 2
        for (int kk = 0; kk < 64; kk += 2) {
            ulonglong2 a0 = *(const ulonglong2*)&Ws[kk * 64 + tx * 4];
            ulonglong2 a1 = *(const ulonglong2*)&Ws[kk * 64 + 32 + tx * 4];
            ulonglong2 b0 = *(const ulonglong2*)&Ws[(kk + 1) * 64 + tx * 4];
            ulonglong2 b1 = *(const ulonglong2*)&Ws[(kk + 1) * 64 + 32 + tx * 4];
            #pragma unroll
            for (int i = 0; i < 8; i++) {
                float2 xp = *(const float2*)&Xs[(ty + 16 * i) * XPITCH + kk];
                unsigned long long ax = dup2(xp.x);
                unsigned long long ay = dup2(xp.y);
                ffma2(acc[i][0], ax, a0.x);
                ffma2(acc[i][1], ax, a0.y);
                ffma2(acc[i][2], ax, a1.x);
                ffma2(acc[i][3], ax, a1.y);
                ffma2(acc[i][0], ay, b0.x);
                ffma2(acc[i][1], ay, b0.y);
                ffma2(acc[i][2], ay, b1.x);
                ffma2(acc[i][3], ay, b1.y);
            }
        }
        __syncthreads();
    }

    #pragma unroll
    for (int i = 0; i < 8; i++) {
        int node = n0 + ty + 16 * i;
        if (node < N) {
            float2 p0 = u2f2(acc[i][0]), p1 = u2f2(acc[i][1]);   // rel cols tx*4..+3
            float2 p2 = u2f2(acc[i][2]), p3 = u2f2(acc[i][3]);   // root cols 32+tx*4..+3
            __half2 h0 = __float22half2_rn(p0);
            __half2 h1 = __float22half2_rn(p1);
            *(uint2*)&g_xwh[node * 32 + tx * 4] =
                make_uint2(*(unsigned*)&h0, *(unsigned*)&h1);
            *(float4*)&g_xroot[node * 32 + tx * 4] = make_float4(p2.x, p2.y, p3.x, p3.y);
        }
    }

    // epilogue: zero this block's slices of g_sum1 / g_sum2
    {
        int node = n0 + t;
        if (node < N) {
            float4 z = make_float4(0.f, 0.f, 0.f, 0.f);
            float4* s1 = (float4*)&g_sum1[node * 32];
            #pragma unroll
            for (int q = 0; q < 8; q++) s1[q] = z;
            float4* s2 = (float4*)&g_sum2[node * 8];
            s2[0] = z; s2[1] = z;
        }
    }
}

// ---- edge pass 1 (weighted): 8 threads/edge, 8B f16 gather + RED.128 ----
__global__ void __launch_bounds__(256) k_edge1(int E) {
    int t = blockIdx.x * 256 + threadIdx.x;
    int e = t >> 3, p = t & 7;
    if (e >= E) return;
    int4 sdw = g_sdw[e];
    float w = __int_as_float(sdw.z);
    uint2 hv = *(const uint2*)&g_xwh[sdw.x * 32 + p * 4];   // 4 halves = 8B
    float2 f0 = __half22float2(*(__half2*)&hv.x);
    float2 f1 = __half22float2(*(__half2*)&hv.y);
    float4 v = make_float4(f0.x * w, f0.y * w, f1.x * w, f1.y * w);
    red_add4(&g_sum1[sdw.y * 32 + p * 4], v);
}

// ---- combine layer 1 + project layer 2 ----
__global__ void __launch_bounds__(256) k_comb1(
    const float* __restrict__ b1,
    const float* __restrict__ Wrel2,    // [32][5]
    const float* __restrict__ Wroot2,   // [32][5]
    int N)
{
    __shared__ float sW[352];
    int t = threadIdx.x;
    for (int i = t; i < 352; i += 256) {
        sW[i] = (i < 160) ? Wrel2[i]
              : (i < 320) ? Wroot2[i - 160]
                          : b1[i - 320];
    }
    __syncthreads();

    int node = blockIdx.x * 256 + t;
    if (node >= N) return;

    float inv = 1.0f / fmaxf(g_cnt[node], 1.0f);
    const float4* sp = (const float4*)&g_sum1[node * 32];
    const float4* rp = (const float4*)&g_xroot[node * 32];

    float h[32];
    #pragma unroll
    for (int q = 0; q < 8; q++) {
        float4 s4 = sp[q];
        float4 r4 = rp[q];
        h[4 * q + 0] = fmaxf(s4.x * inv + r4.x + sW[320 + 4 * q + 0], 0.f);
        h[4 * q + 1] = fmaxf(s4.y * inv + r4.y + sW[320 + 4 * q + 1], 0.f);
        h[4 * q + 2] = fmaxf(s4.z * inv + r4.z + sW[320 + 4 * q + 2], 0.f);
        h[4 * q + 3] = fmaxf(s4.w * inv + r4.w + sW[320 + 4 * q + 3], 0.f);
    }

    float hr[5] = {0.f, 0.f, 0.f, 0.f, 0.f};
    float ho[5] = {0.f, 0.f, 0.f, 0.f, 0.f};
    #pragma unroll
    for (int j = 0; j < 32; j++) {
        float hv = h[j];
        #pragma unroll
        for (int c = 0; c < 5; c++) {
            hr[c] += hv * sW[j * 5 + c];
            ho[c] += hv * sW[160 + j * 5 + c];
        }
    }
    *(float4*)&g_hr[node * 8 + 0]    = make_float4(hr[0], hr[1], hr[2], hr[3]);
    *(float4*)&g_hr[node * 8 + 4]    = make_float4(hr[4], 0.f, 0.f, 0.f);
    *(float4*)&g_hroot[node * 8 + 0] = make_float4(ho[0], ho[1], ho[2], ho[3]);
    *(float4*)&g_hroot[node * 8 + 4] = make_float4(ho[4], 0.f, 0.f, 0.f);
}

// ---- edge pass 2: 2 threads/edge, LDG.128 + RED.128 (fp32) ----
__global__ void __launch_bounds__(256) k_edge2(int E) {
    int t = blockIdx.x * 256 + threadIdx.x;
    int e = t >> 1, p = t & 1;
    if (e >= E) return;
    int4 sdw = g_sdw[e];
    float4 v = *(const float4*)&g_hr[sdw.x * 8 + p * 4];
    red_add4(&g_sum2[sdw.y * 8 + p * 4], v);
}

// ---- combine layer 2 + log_softmax ----
__global__ void __launch_bounds__(256) k_final(
    const float* __restrict__ b2,
    float* __restrict__ out,
    int N)
{
    int node = blockIdx.x * 256 + threadIdx.x;
    if (node >= N) return;
    float inv = 1.0f / fmaxf(g_cnt[node], 1.0f);
    float v[5];
    #pragma unroll
    for (int c = 0; c < 5; c++)
        v[c] = g_sum2[node * 8 + c] * inv + g_hroot[node * 8 + c] + b2[c];

    float m = v[0];
    #pragma unroll
    for (int c = 1; c < 5; c++) m = fmaxf(m, v[c]);
    float sum = 0.f;
    #pragma unroll
    for (int c = 0; c < 5; c++) sum += expf(v[c] - m);
    float lse = m + logf(sum);
    #pragma unroll
    for (int c = 0; c < 5; c++) out[node * 5 + c] = v[c] - lse;
}

extern "C" void kernel_launch(void* const* d_in, const int* in_sizes, int n_in,
                              void* d_out, int out_size)
{
    const float* x      = (const float*)d_in[0];
    const int*   ei     = (const int*)d_in[1];
    const float* ew     = (const float*)d_in[2];
    const float* Wrel1  = (const float*)d_in[3];
    const float* Wroot1 = (const float*)d_in[4];
    const float* b1     = (const float*)d_in[5];
    const float* Wrel2  = (const float*)d_in[6];
    const float* Wroot2 = (const float*)d_in[7];
    const float* b2     = (const float*)d_in[8];
    float*       out    = (float*)d_out;

    int N = out_size / 5;          // output [N,5]
    int E = in_sizes[1] / 2;       // edge_index [2,E]

    const int GEMM_SMEM = (4096 + 128 * XPITCH) * 4;   // 51200 B
    cudaFuncSetAttribute(k_gemm1, cudaFuncAttributeMaxDynamicSharedMemorySize, GEMM_SMEM);

    static cudaStream_t s2 = nullptr;
    static cudaEvent_t evFork = nullptr, evJoin = nullptr;
    if (!s2) {
        cudaStreamCreateWithFlags(&s2, cudaStreamNonBlocking);
        cudaEventCreateWithFlags(&evFork, cudaEventDisableTiming);
        cudaEventCreateWithFlags(&evJoin, cudaEventDisableTiming);
    }

    // fork: {zc -> unpack} on s2, gemm1 on main stream, join before edge1
    cudaEventRecord(evFork, 0);
    cudaStreamWaitEvent(s2, evFork, 0);
    k_zc    <<<(N + 255) / 256, 256, 0, s2>>>(ei, N);
    k_unpack<<<(E + 255) / 256, 256, 0, s2>>>(ei, ew, E, N);
    cudaEventRecord(evJoin, s2);

    k_gemm1 <<<(N + 127) / 128, 128, GEMM_SMEM>>>(x, Wrel1, Wroot1, N);
    cudaStreamWaitEvent(0, evJoin, 0);

    k_edge1 <<<(E * 8 + 255) / 256, 256>>>(E);
    k_comb1 <<<(N + 255) / 256, 256>>>(b1, Wrel2, Wroot2, N);
    k_edge2 <<<(E * 2 + 255) / 256, 256>>>(E);
    k_final <<<(N + 255) / 256, 256>>>(b2, out, N);
}